// round 4
// baseline (speedup 1.0000x reference)
#include <cuda_runtime.h>

#define IMG 256
#define MSAMP 1920
#define BATCH 64

typedef unsigned long long u64t;

// Scratch (no allocations allowed): phase matrices + density-weighted kspace.
__device__ float2 g_Ax[MSAMP * IMG];   // exp(-2i*pi*kx*(i-128))
__device__ float2 g_Ay[MSAMP * IMG];   // exp(-2i*pi*ky*(j-128))
__device__ float2 g_kw[BATCH * MSAMP]; // kspace * density

// ---- packed f32x2 helpers (sm_103a FFMA2) ---------------------------------
__device__ __forceinline__ u64t pk2(float lo, float hi) {
    u64t r;
    asm("mov.b64 %0, {%1, %2};" : "=l"(r) : "f"(lo), "f"(hi));
    return r;
}
__device__ __forceinline__ void fma2(u64t& d, u64t a, u64t b) {
    asm("fma.rn.f32x2 %0, %1, %2, %0;" : "+l"(d) : "l"(a), "l"(b));
}
__device__ __forceinline__ float2 unpk2(u64t v) {
    float lo, hi;
    asm("mov.b64 {%0, %1}, %2;" : "=f"(lo), "=f"(hi) : "l"(v));
    return make_float2(lo, hi);
}

// ---------------------------------------------------------------------------
// Phase matrices: Ax[m,i] = exp(-2i*pi*kx_m*(i-128)), same for Ay with ky.
// ---------------------------------------------------------------------------
__global__ void phase_kernel(const float* __restrict__ samples) {
    int idx = blockIdx.x * blockDim.x + threadIdx.x; // m*IMG + i
    if (idx >= MSAMP * IMG) return;
    int m = idx >> 8;
    int i = idx & 255;
    float g = (float)i - 128.0f;
    float kx = samples[2 * m];
    float ky = samples[2 * m + 1];
    const float TWO_PI = 6.28318530717958647692f;
    float sx, cx, sy, cy;
    sincosf(TWO_PI * kx * g, &sx, &cx);
    sincosf(TWO_PI * ky * g, &sy, &cy);
    g_Ax[idx] = make_float2(cx, -sx);
    g_Ay[idx] = make_float2(cy, -sy);
}

// ---------------------------------------------------------------------------
// Forward NUFFT fused with j-reduction and density weighting:
//   kw[b,m] = density[m] * sum_j Ay[m,j] * (sum_i Ax[m,i] * x[b,i,j])
// CTA: one batch b, 16 samples m. 4 warps; each warp owns 4 m's and keeps the
// full 256-wide t-row packed in registers (8 complex per lane).
// ---------------------------------------------------------------------------
__global__ __launch_bounds__(128, 4) void forward_kernel(
    const float* __restrict__ xr, const float* __restrict__ xi,
    const float* __restrict__ density)
{
    __shared__ float2 sx[8 * 256];   // 8 rows of x[b], complex
    __shared__ float2 sA[16 * 8];    // Ax chunk: 16 m x 8 i

    int b    = blockIdx.y;
    int m0   = blockIdx.x * 16;
    int tid  = threadIdx.x;
    int warp = tid >> 5;
    int lane = tid & 31;

    u64t acc[4][8];
#pragma unroll
    for (int mm = 0; mm < 4; mm++)
#pragma unroll
        for (int r = 0; r < 8; r++) acc[mm][r] = 0ull;

    int xbase = b * (IMG * IMG);

    for (int it = 0; it < 32; ++it) {
        int i0 = it * 8;
        __syncthreads();
        int tb = xbase + i0 * 256;
#pragma unroll
        for (int u = tid; u < 2048; u += 128)
            sx[u] = make_float2(xr[tb + u], xi[tb + u]);
        {
            int mm = tid >> 3, ii = tid & 7;   // tid < 128 always
            sA[tid] = g_Ax[(m0 + mm) * IMG + i0 + ii];
        }
        __syncthreads();

#pragma unroll
        for (int ii = 0; ii < 8; ++ii) {
            u64t xvs[8], xvr[8];
#pragma unroll
            for (int r = 0; r < 8; r++) {
                float2 xv = sx[ii * 256 + lane + 32 * r];
                xvs[r] = pk2(xv.x, xv.y);
                xvr[r] = pk2(xv.y, xv.x);
            }
#pragma unroll
            for (int mm = 0; mm < 4; mm++) {
                float2 a = sA[(warp * 4 + mm) * 8 + ii];
                u64t A1 = pk2(a.x, a.x);
                u64t A2 = pk2(-a.y, a.y);
#pragma unroll
                for (int r = 0; r < 8; r++) {
                    fma2(acc[mm][r], A1, xvs[r]);
                    fma2(acc[mm][r], A2, xvr[r]);
                }
            }
        }
    }

    // j-reduction: kspace[b,m] = sum_j Ay[m,j] * t[j]; then * density.
#pragma unroll
    for (int mm = 0; mm < 4; mm++) {
        int m = m0 + warp * 4 + mm;
        float sre = 0.f, sim = 0.f;
#pragma unroll
        for (int r = 0; r < 8; r++) {
            float2 ay = g_Ay[m * IMG + lane + 32 * r];
            float2 t  = unpk2(acc[mm][r]);
            sre = fmaf(ay.x, t.x, fmaf(-ay.y, t.y, sre));
            sim = fmaf(ay.x, t.y, fmaf( ay.y, t.x, sim));
        }
#pragma unroll
        for (int off = 16; off > 0; off >>= 1) {
            sre += __shfl_down_sync(0xffffffffu, sre, off);
            sim += __shfl_down_sync(0xffffffffu, sim, off);
        }
        if (lane == 0) {
            float d = density[m];
            g_kw[b * MSAMP + m] = make_float2(sre * d, sim * d);
        }
    }
}

// ---------------------------------------------------------------------------
// Adjoint: adj[b,i,j] = (1/65536) * sum_m conj(Ax[m,i]) * kw[b,m] * conj(Ay[m,j])
// Per-batch GEMM, 64x64 output tile per CTA, K=1920 in chunks of 16.
// W[m,j] = kw[b,m]*conj(Ay[m,j]) is formed on the fly while staging.
// ---------------------------------------------------------------------------
__global__ __launch_bounds__(128, 4) void adjoint_kernel(float2* __restrict__ out)
{
    __shared__ float2 sA[16 * 64]; // conj(Ax)[kk][i]
    __shared__ float2 sW[16 * 64]; // kw*conj(Ay)[kk][j]

    int b   = blockIdx.z;
    int i0  = blockIdx.y * 64;
    int j0  = blockIdx.x * 64;
    int tid = threadIdx.x;
    int ti  = tid >> 4;    // 0..7
    int tj  = tid & 15;    // 0..15

    u64t acc[8][4];
#pragma unroll
    for (int a = 0; a < 8; a++)
#pragma unroll
        for (int c = 0; c < 4; c++) acc[a][c] = 0ull;

    for (int k0 = 0; k0 < MSAMP; k0 += 16) {
        __syncthreads();
#pragma unroll
        for (int u = tid; u < 1024; u += 128) {
            int kk  = u >> 6;
            int idx = u & 63;
            int m   = k0 + kk;
            float2 ax = g_Ax[m * IMG + i0 + idx];
            sA[u] = make_float2(ax.x, -ax.y);
            float2 ay = g_Ay[m * IMG + j0 + idx];
            float2 w  = g_kw[b * MSAMP + m];
            // w * conj(ay)
            sW[u] = make_float2(fmaf(w.x, ay.x,  w.y * ay.y),
                                fmaf(w.y, ay.x, -w.x * ay.y));
        }
        __syncthreads();

        const float4* sW4 = reinterpret_cast<const float4*>(sW);
#pragma unroll
        for (int kk = 0; kk < 16; ++kk) {
            int wbase = (kk * 64 + tj * 4) >> 1;
            float4 w01 = sW4[wbase];
            float4 w23 = sW4[wbase + 1];
            u64t W1[4], W2[4];
            W1[0] = pk2(w01.x, w01.x); W2[0] = pk2(-w01.y, w01.y);
            W1[1] = pk2(w01.z, w01.z); W2[1] = pk2(-w01.w, w01.w);
            W1[2] = pk2(w23.x, w23.x); W2[2] = pk2(-w23.y, w23.y);
            W1[3] = pk2(w23.z, w23.z); W2[3] = pk2(-w23.w, w23.w);
#pragma unroll
            for (int a = 0; a < 8; a++) {
                float2 av = sA[kk * 64 + ti + 8 * a];
                u64t avs = pk2(av.x, av.y);
                u64t avr = pk2(av.y, av.x);
#pragma unroll
                for (int c = 0; c < 4; c++) {
                    fma2(acc[a][c], W1[c], avs);
                    fma2(acc[a][c], W2[c], avr);
                }
            }
        }
    }

    const float s = 1.0f / 65536.0f;
#pragma unroll
    for (int a = 0; a < 8; a++) {
        int i = i0 + ti + 8 * a;
#pragma unroll
        for (int c = 0; c < 4; c++) {
            int j = j0 + tj * 4 + c;
            float2 v = unpk2(acc[a][c]);
            out[b * (IMG * IMG) + i * IMG + j] = make_float2(v.x * s, v.y * s);
        }
    }
}

// ---------------------------------------------------------------------------
extern "C" void kernel_launch(void* const* d_in, const int* in_sizes, int n_in,
                              void* d_out, int out_size)
{
    const float* xr      = (const float*)d_in[0];
    const float* xi      = (const float*)d_in[1];
    const float* samples = (const float*)d_in[2];
    const float* density = (const float*)d_in[3];
    float2* out = (float2*)d_out;

    phase_kernel<<<(MSAMP * IMG + 255) / 256, 256>>>(samples);
    forward_kernel<<<dim3(MSAMP / 16, BATCH), 128>>>(xr, xi, density);
    adjoint_kernel<<<dim3(4, 4, BATCH), 128>>>(out);
}

// round 5
// speedup vs baseline: 6.5793x; 6.5793x over previous
#include <cuda_runtime.h>

#define IMG 256
#define MSAMP 1920
#define BATCH 64
#define NF 512                 // FFT size
#define NF2 (NF*NF)            // 262144
#define KSPLIT 6               // T-build K partitions (1920 = 6*320)

typedef unsigned long long u64t;

// ---------------------------------------------------------------------------
// Device scratch (static globals; no runtime allocation allowed)
// ---------------------------------------------------------------------------
__device__ float2 g_ex[MSAMP * NF];          // d_m/65536 * exp(+2i pi kx_m p)
__device__ float2 g_ey[MSAMP * NF];          // exp(+2i pi ky_m q)
__device__ float2 g_T[NF2];                  // Toeplitz kernel T[p][q]
__device__ float2 g_Tpart[KSPLIT * NF2];     // K-split partial sums
__device__ float2 g_Ttmp[NF2];               // T after row FFT (transposed)
__device__ float2 g_TFt[NF2];                // FFT2(T), stored [v][u] (v-major)
__device__ float2 g_tw[NF];                  // W512^k = exp(-2i pi k/512)
__device__ float2 g_buf1[BATCH * NF2];       // ping
__device__ float2 g_buf2[BATCH * NF2];       // pong

// ---- packed f32x2 helpers (sm_103a FFMA2) ---------------------------------
__device__ __forceinline__ u64t pk2(float lo, float hi) {
    u64t r; asm("mov.b64 %0, {%1, %2};" : "=l"(r) : "f"(lo), "f"(hi)); return r;
}
__device__ __forceinline__ void fma2(u64t& d, u64t a, u64t b) {
    asm("fma.rn.f32x2 %0, %1, %2, %0;" : "+l"(d) : "l"(a), "l"(b));
}
__device__ __forceinline__ float2 unpk2(u64t v) {
    float lo, hi; asm("mov.b64 {%0, %1}, %2;" : "=f"(lo), "=f"(hi) : "l"(v));
    return make_float2(lo, hi);
}

// ---- complex helpers ------------------------------------------------------
__device__ __forceinline__ float2 cadd(float2 a, float2 b){ return make_float2(a.x+b.x, a.y+b.y); }
__device__ __forceinline__ float2 csub(float2 a, float2 b){ return make_float2(a.x-b.x, a.y-b.y); }
__device__ __forceinline__ float2 cmulf(float2 a, float2 b){
    return make_float2(fmaf(a.x,b.x,-a.y*b.y), fmaf(a.x,b.y, a.y*b.x));
}
// multiply by (fwd: -i) / (inv: +i)
template<int DIR> __device__ __forceinline__ float2 mul_i(float2 a){
    return (DIR > 0) ? make_float2(a.y, -a.x) : make_float2(-a.y, a.x);
}
// twiddle multiply with direction (DIR<0: conj(tw))
template<int DIR> __device__ __forceinline__ float2 ctw(float2 a, float2 tw){
    float ty = (DIR > 0) ? tw.y : -tw.y;
    return make_float2(fmaf(a.x,tw.x,-a.y*ty), fmaf(a.x,ty, a.y*tw.x));
}

// ---- radix-8 DFT (in place), DIR=+1 forward e^{-}, DIR=-1 inverse ---------
template<int DIR> __device__ __forceinline__ void dft8(float2* a){
    float2 F0=cadd(a[0],a[4]), F1=csub(a[0],a[4]);
    float2 G0=cadd(a[2],a[6]), G1=csub(a[2],a[6]);
    float2 E0=cadd(F0,G0),     E2=csub(F0,G0);
    float2 G1i = mul_i<DIR>(G1);
    float2 E1=cadd(F1,G1i),    E3=csub(F1,G1i);

    float2 H0=cadd(a[1],a[5]), H1=csub(a[1],a[5]);
    float2 I0=cadd(a[3],a[7]), I1=csub(a[3],a[7]);
    float2 O0=cadd(H0,I0),     O2=csub(H0,I0);
    float2 I1i = mul_i<DIR>(I1);
    float2 O1=cadd(H1,I1i),    O3=csub(H1,I1i);

    const float s = 0.70710678118654752440f;
    float2 T1 = (DIR > 0) ? make_float2(s*(O1.x+O1.y), s*(O1.y-O1.x))
                          : make_float2(s*(O1.x-O1.y), s*(O1.y+O1.x));
    float2 T2 = mul_i<DIR>(O2);
    float2 T3 = (DIR > 0) ? make_float2(s*(O3.y-O3.x), -s*(O3.x+O3.y))
                          : make_float2(-s*(O3.x+O3.y), s*(O3.x-O3.y));

    a[0]=cadd(E0,O0); a[4]=csub(E0,O0);
    a[1]=cadd(E1,T1); a[5]=csub(E1,T1);
    a[2]=cadd(E2,T2); a[6]=csub(E2,T2);
    a[3]=cadd(E3,T3); a[7]=csub(E3,T3);
}

// ---------------------------------------------------------------------------
// Twiddle table: g_tw[k] = exp(-2i pi k / 512)
// ---------------------------------------------------------------------------
__global__ void tw_kernel() {
    int k = blockIdx.x * blockDim.x + threadIdx.x;
    if (k >= NF) return;
    float sp, cp;
    sincospif((float)k / 256.0f, &sp, &cp);   // angle = pi*k/256
    g_tw[k] = make_float2(cp, -sp);
}

// ---------------------------------------------------------------------------
// ex[m][idx] = d_m/65536 * exp(+2i pi kx_m p),  ey[m][idx] = exp(+2i pi ky_m q)
// idx -> p: idx<256 ? idx : idx-512 ; idx==256 -> 0 (unused offset)
// ---------------------------------------------------------------------------
__global__ void build_exp_kernel(const float* __restrict__ samples,
                                 const float* __restrict__ density) {
    int idx = blockIdx.x * blockDim.x + threadIdx.x;  // m*512 + t
    if (idx >= MSAMP * NF) return;
    int m = idx >> 9;
    int t = idx & (NF - 1);
    if (t == 256) { g_ex[idx] = make_float2(0.f,0.f); g_ey[idx] = make_float2(0.f,0.f); return; }
    float p = (t < 256) ? (float)t : (float)(t - 512);
    const float TWO_PI = 6.28318530717958647692f;
    float kx = samples[2*m], ky = samples[2*m+1];
    float sx, cx, sy, cy;
    sincosf(TWO_PI * kx * p, &sx, &cx);
    sincosf(TWO_PI * ky * p, &sy, &cy);
    float d = density[m] * (1.0f / 65536.0f);
    g_ex[idx] = make_float2(cx * d, sx * d);
    g_ey[idx] = make_float2(cy, sy);
}

// ---------------------------------------------------------------------------
// T partials: Tpart[kz][p][q] = sum_{m in slice} ex[m,p] * ey[m,q]
// 64x64 tile per CTA, 128 threads, FFMA2 inner loop.
// ---------------------------------------------------------------------------
__global__ __launch_bounds__(128, 4) void tpart_kernel() {
    __shared__ float2 sE[16 * 64]; // ex chunk [kk][p]
    __shared__ float2 sF[16 * 64]; // ey chunk [kk][q]

    int p0 = blockIdx.y * 64;
    int q0 = blockIdx.x * 64;
    int m0 = blockIdx.z * (MSAMP / KSPLIT);
    int tid = threadIdx.x;
    int ti = tid >> 4;   // 0..7
    int tj = tid & 15;   // 0..15

    u64t acc[8][4];
#pragma unroll
    for (int a = 0; a < 8; a++)
#pragma unroll
        for (int c = 0; c < 4; c++) acc[a][c] = 0ull;

    for (int k0 = 0; k0 < MSAMP / KSPLIT; k0 += 16) {
        __syncthreads();
#pragma unroll
        for (int u = tid; u < 1024; u += 128) {
            int kk  = u >> 6;
            int idx = u & 63;
            int m   = m0 + k0 + kk;
            sE[u] = g_ex[m * NF + p0 + idx];
            sF[u] = g_ey[m * NF + q0 + idx];
        }
        __syncthreads();

        const float4* sF4 = reinterpret_cast<const float4*>(sF);
#pragma unroll
        for (int kk = 0; kk < 16; ++kk) {
            int wbase = (kk * 64 + tj * 4) >> 1;
            float4 w01 = sF4[wbase];
            float4 w23 = sF4[wbase + 1];
            u64t W1[4], W2[4];
            W1[0] = pk2(w01.x, w01.x); W2[0] = pk2(-w01.y, w01.y);
            W1[1] = pk2(w01.z, w01.z); W2[1] = pk2(-w01.w, w01.w);
            W1[2] = pk2(w23.x, w23.x); W2[2] = pk2(-w23.y, w23.y);
            W1[3] = pk2(w23.z, w23.z); W2[3] = pk2(-w23.w, w23.w);
#pragma unroll
            for (int a = 0; a < 8; a++) {
                float2 av = sE[kk * 64 + ti + 8 * a];
                u64t avs = pk2(av.x, av.y);
                u64t avr = pk2(av.y, av.x);
#pragma unroll
                for (int c = 0; c < 4; c++) {
                    fma2(acc[a][c], W1[c], avs);
                    fma2(acc[a][c], W2[c], avr);
                }
            }
        }
    }

    float2* outp = g_Tpart + blockIdx.z * NF2;
#pragma unroll
    for (int a = 0; a < 8; a++) {
        int p = p0 + ti + 8 * a;
#pragma unroll
        for (int c = 0; c < 4; c++) {
            int q = q0 + tj * 4 + c;
            outp[p * NF + q] = unpk2(acc[a][c]);
        }
    }
}

__global__ void treduce_kernel() {
    int idx = blockIdx.x * blockDim.x + threadIdx.x;
    if (idx >= NF2) return;
    float2 s = make_float2(0.f, 0.f);
#pragma unroll
    for (int z = 0; z < KSPLIT; z++) s = cadd(s, g_Tpart[z * NF2 + idx]);
    g_T[idx] = s;
}

// ---------------------------------------------------------------------------
// Generic 512-pt Stockham radix-8 FFT pass. 64 threads per line, 4 lines/CTA.
// MODE 0: x fwd pass1 (zero-padded load from xr/xi), write buf1[b][v][i] (T)
// MODE 1: x fwd pass2 (zero-padded load buf1), *TFt at write, buf2[b][u][v]
// MODE 2: x inv pass1 (load buf2), write only j<256: buf1[b][j][u]
// MODE 3: x inv pass2 (load buf1), write only i<256: out, scaled 1/512^2
// MODE 4: T pass1 (load g_T), write Ttmp[v][p]
// MODE 5: T pass2 (load Ttmp), write TFt[v][u]
// DIR: +1 forward, -1 inverse.
// ---------------------------------------------------------------------------
#define SPAD(x) ((x) + ((x) >> 3))

template<int MODE, int DIR>
__global__ __launch_bounds__(256) void fft_pass_kernel(
    const float* __restrict__ xr, const float* __restrict__ xi,
    float2* __restrict__ out)
{
    __shared__ float2 s_tw[NF];
    __shared__ float2 s_buf[4][576];

    int t = threadIdx.x;
    int grp = t >> 6;          // line within CTA
    int i   = t & 63;          // butterfly index

    for (int u = t; u < NF; u += 256) s_tw[u] = g_tw[u];

    int line = blockIdx.x * 4 + grp;

    // ---- decode line, load 8 inputs: a[r] = in[i + 64r] ----
    float2 a[8];
    int b = 0, l2 = 0;
    if (MODE == 0) {
        b = line >> 8; l2 = line & 255;                 // l2 = image row i
        const float* pr = xr + ((b << 16) + (l2 << 8));
        const float* pi = xi + ((b << 16) + (l2 << 8));
#pragma unroll
        for (int r = 0; r < 8; r++) {
            if (r < 4) { int n = i + (r << 6); a[r] = make_float2(pr[n], pi[n]); }
            else a[r] = make_float2(0.f, 0.f);
        }
    } else if (MODE == 1) {
        b = line >> 9; l2 = line & 511;                 // l2 = v
        const float2* src = g_buf1 + b * NF2 + l2 * NF;
#pragma unroll
        for (int r = 0; r < 8; r++)
            a[r] = (r < 4) ? src[i + (r << 6)] : make_float2(0.f, 0.f);
    } else if (MODE == 2) {
        b = line >> 9; l2 = line & 511;                 // l2 = u
        const float2* src = g_buf2 + b * NF2 + l2 * NF;
#pragma unroll
        for (int r = 0; r < 8; r++) a[r] = src[i + (r << 6)];
    } else if (MODE == 3) {
        b = line >> 8; l2 = line & 255;                 // l2 = j
        const float2* src = g_buf1 + b * NF2 + l2 * NF;
#pragma unroll
        for (int r = 0; r < 8; r++) a[r] = src[i + (r << 6)];
    } else if (MODE == 4) {
        l2 = line;                                      // l2 = p
        const float2* src = g_T + l2 * NF;
#pragma unroll
        for (int r = 0; r < 8; r++) a[r] = src[i + (r << 6)];
    } else { // MODE 5
        l2 = line;                                      // l2 = v
        const float2* src = g_Ttmp + l2 * NF;
#pragma unroll
        for (int r = 0; r < 8; r++) a[r] = src[i + (r << 6)];
    }

    // ---- stage 0 (L=1): no twiddle ----
    dft8<DIR>(a);
#pragma unroll
    for (int r = 0; r < 8; r++) s_buf[grp][SPAD(8 * i + r)] = a[r];
    __syncthreads();

    // ---- stage 1 (L=8): twiddle W512^{8*p*r}, p = i&7 ----
#pragma unroll
    for (int r = 0; r < 8; r++) a[r] = s_buf[grp][SPAD(i + 64 * r)];
    {
        int p = i & 7;
#pragma unroll
        for (int r = 1; r < 8; r++) a[r] = ctw<DIR>(a[r], s_tw[(p * r) << 3]);
    }
    dft8<DIR>(a);
    __syncthreads();
#pragma unroll
    for (int r = 0; r < 8; r++)
        s_buf[grp][SPAD(((i >> 3) << 6) + (r << 3) + (i & 7))] = a[r];
    __syncthreads();

    // ---- stage 2 (L=64): twiddle W512^{i*r} ----
#pragma unroll
    for (int r = 0; r < 8; r++) a[r] = s_buf[grp][SPAD(i + 64 * r)];
#pragma unroll
    for (int r = 1; r < 8; r++) a[r] = ctw<DIR>(a[r], s_tw[i * r]);
    dft8<DIR>(a);

    // ---- store: output index k = r*64 + i ----
    if (MODE == 0) {
        float2* dst = g_buf1 + b * NF2;                 // [v][i_row]
#pragma unroll
        for (int r = 0; r < 8; r++) dst[((r << 6) + i) * NF + l2] = a[r];
    } else if (MODE == 1) {
        float2* dst = g_buf2 + b * NF2;                 // [u][v]
        const float2* tf = g_TFt + l2 * NF;             // TFt[v][u]
#pragma unroll
        for (int r = 0; r < 8; r++) {
            int u = (r << 6) + i;
            dst[u * NF + l2] = cmulf(a[r], tf[u]);
        }
    } else if (MODE == 2) {
        float2* dst = g_buf1 + b * NF2;                 // [j][u], j<256 only
#pragma unroll
        for (int r = 0; r < 4; r++) dst[((r << 6) + i) * NF + l2] = a[r];
    } else if (MODE == 3) {
        const float s = 1.0f / 262144.0f;               // 1/512^2
        float2* dst = out + (b << 16);                  // [i_row][j], i<256
#pragma unroll
        for (int r = 0; r < 4; r++) {
            int irow = (r << 6) + i;
            dst[(irow << 8) + l2] = make_float2(a[r].x * s, a[r].y * s);
        }
    } else if (MODE == 4) {
#pragma unroll
        for (int r = 0; r < 8; r++) g_Ttmp[((r << 6) + i) * NF + l2] = a[r];
    } else { // MODE 5: TFt[v][u]
        float2* dst = g_TFt + l2 * NF;
#pragma unroll
        for (int r = 0; r < 8; r++) dst[(r << 6) + i] = a[r];
    }
}

// ---------------------------------------------------------------------------
extern "C" void kernel_launch(void* const* d_in, const int* in_sizes, int n_in,
                              void* d_out, int out_size)
{
    const float* xr      = (const float*)d_in[0];
    const float* xi      = (const float*)d_in[1];
    const float* samples = (const float*)d_in[2];
    const float* density = (const float*)d_in[3];
    float2* out = (float2*)d_out;

    tw_kernel<<<2, 256>>>();
    build_exp_kernel<<<(MSAMP * NF + 255) / 256, 256>>>(samples, density);
    tpart_kernel<<<dim3(8, 8, KSPLIT), 128>>>();
    treduce_kernel<<<(NF2 + 255) / 256, 256>>>();

    // FFT2 of Toeplitz kernel
    fft_pass_kernel<4, 1><<<NF / 4, 256>>>(nullptr, nullptr, nullptr);
    fft_pass_kernel<5, 1><<<NF / 4, 256>>>(nullptr, nullptr, nullptr);

    // x: forward FFT2 (zero-padded), multiply by TF, inverse FFT2, crop
    fft_pass_kernel<0, 1><<<BATCH * 256 / 4, 256>>>(xr, xi, nullptr);
    fft_pass_kernel<1, 1><<<BATCH * 512 / 4, 256>>>(nullptr, nullptr, nullptr);
    fft_pass_kernel<2, -1><<<BATCH * 512 / 4, 256>>>(nullptr, nullptr, nullptr);
    fft_pass_kernel<3, -1><<<BATCH * 256 / 4, 256>>>(nullptr, nullptr, out);
}

// round 8
// speedup vs baseline: 10.0847x; 1.5328x over previous
#include <cuda_runtime.h>

#define IMG 256
#define MSAMP 1920
#define BATCH 64
#define NF 512                 // FFT size
#define NF2 (NF*NF)            // 262144
#define KSPLIT 12              // T-build K partitions (1920 = 12*160)

typedef unsigned long long u64t;

// ---------------------------------------------------------------------------
// Device scratch (static globals; no runtime allocation allowed)
// ---------------------------------------------------------------------------
__device__ float2 g_ex[MSAMP * NF];          // d_m/65536 * exp(+2i pi kx_m p)
__device__ float2 g_ey[MSAMP * NF];          // exp(+2i pi ky_m q)
__device__ float2 g_Tpart[KSPLIT * NF2];     // K-split partial sums of T
__device__ float2 g_Ttmp[NF2];               // T after row FFT: [v][p]
__device__ float2 g_TFt[NF2];                // FFT2(T), stored [u][v]
__device__ float2 g_tw[NF];                  // W512^k = exp(-2i pi k/512)
__device__ float2 g_buf1[BATCH * NF2];       // ping
__device__ float2 g_buf2[BATCH * NF2];       // pong

// ---- packed f32x2 helpers (sm_103a FFMA2) ---------------------------------
__device__ __forceinline__ u64t pk2(float lo, float hi) {
    u64t r; asm("mov.b64 %0, {%1, %2};" : "=l"(r) : "f"(lo), "f"(hi)); return r;
}
__device__ __forceinline__ void fma2(u64t& d, u64t a, u64t b) {
    asm("fma.rn.f32x2 %0, %1, %2, %0;" : "+l"(d) : "l"(a), "l"(b));
}
__device__ __forceinline__ float2 unpk2(u64t v) {
    float lo, hi; asm("mov.b64 {%0, %1}, %2;" : "=f"(lo), "=f"(hi) : "l"(v));
    return make_float2(lo, hi);
}

// ---- complex helpers ------------------------------------------------------
__device__ __forceinline__ float2 cadd(float2 a, float2 b){ return make_float2(a.x+b.x, a.y+b.y); }
__device__ __forceinline__ float2 csub(float2 a, float2 b){ return make_float2(a.x-b.x, a.y-b.y); }
__device__ __forceinline__ float2 cmulf(float2 a, float2 b){
    return make_float2(fmaf(a.x,b.x,-a.y*b.y), fmaf(a.x,b.y, a.y*b.x));
}
template<int DIR> __device__ __forceinline__ float2 mul_i(float2 a){
    return (DIR > 0) ? make_float2(a.y, -a.x) : make_float2(-a.y, a.x);
}
template<int DIR> __device__ __forceinline__ float2 ctw(float2 a, float2 tw){
    float ty = (DIR > 0) ? tw.y : -tw.y;
    return make_float2(fmaf(a.x,tw.x,-a.y*ty), fmaf(a.x,ty, a.y*tw.x));
}

// ---- radix-8 DFT (in place) -----------------------------------------------
template<int DIR> __device__ __forceinline__ void dft8(float2* a){
    float2 F0=cadd(a[0],a[4]), F1=csub(a[0],a[4]);
    float2 G0=cadd(a[2],a[6]), G1=csub(a[2],a[6]);
    float2 E0=cadd(F0,G0),     E2=csub(F0,G0);
    float2 G1i = mul_i<DIR>(G1);
    float2 E1=cadd(F1,G1i),    E3=csub(F1,G1i);

    float2 H0=cadd(a[1],a[5]), H1=csub(a[1],a[5]);
    float2 I0=cadd(a[3],a[7]), I1=csub(a[3],a[7]);
    float2 O0=cadd(H0,I0),     O2=csub(H0,I0);
    float2 I1i = mul_i<DIR>(I1);
    float2 O1=cadd(H1,I1i),    O3=csub(H1,I1i);

    const float s = 0.70710678118654752440f;
    float2 T1 = (DIR > 0) ? make_float2(s*(O1.x+O1.y), s*(O1.y-O1.x))
                          : make_float2(s*(O1.x-O1.y), s*(O1.y+O1.x));
    float2 T2 = mul_i<DIR>(O2);
    float2 T3 = (DIR > 0) ? make_float2(s*(O3.y-O3.x), -s*(O3.x+O3.y))
                          : make_float2(-s*(O3.x+O3.y), s*(O3.x-O3.y));

    a[0]=cadd(E0,O0); a[4]=csub(E0,O0);
    a[1]=cadd(E1,T1); a[5]=csub(E1,T1);
    a[2]=cadd(E2,T2); a[6]=csub(E2,T2);
    a[3]=cadd(E3,T3); a[7]=csub(E3,T3);
}

// ---------------------------------------------------------------------------
__global__ void tw_kernel() {
    int k = blockIdx.x * blockDim.x + threadIdx.x;
    if (k >= NF) return;
    float sp, cp;
    sincospif((float)k / 256.0f, &sp, &cp);
    g_tw[k] = make_float2(cp, -sp);
}

// ---------------------------------------------------------------------------
// ex/ey tables. Compute t in [0,255], mirror-write conj at (512-t)&511.
// Index 256 (offset +-256, never used) is zeroed.
// ---------------------------------------------------------------------------
__global__ void build_exp_kernel(const float* __restrict__ samples,
                                 const float* __restrict__ density) {
    int idx = blockIdx.x * blockDim.x + threadIdx.x;  // m*256 + t
    if (idx >= MSAMP * 256) return;
    int m = idx >> 8;
    int t = idx & 255;
    float p = (float)t;
    const float TWO_PI = 6.28318530717958647692f;
    float kx = samples[2*m], ky = samples[2*m+1];
    float sx, cx, sy, cy;
    sincosf(TWO_PI * kx * p, &sx, &cx);
    sincosf(TWO_PI * ky * p, &sy, &cy);
    float d = density[m] * (1.0f / 65536.0f);
    float2 exv = make_float2(cx * d, sx * d);
    float2 eyv = make_float2(cy, sy);
    g_ex[m * NF + t] = exv;
    g_ey[m * NF + t] = eyv;
    int tm = (NF - t) & (NF - 1);
    g_ex[m * NF + tm] = make_float2(exv.x, -exv.y);
    g_ey[m * NF + tm] = make_float2(eyv.x, -eyv.y);
    if (t == 0) {
        g_ex[m * NF + 256] = make_float2(0.f, 0.f);
        g_ey[m * NF + 256] = make_float2(0.f, 0.f);
    }
}

// ---------------------------------------------------------------------------
// T partials with Hermitian halving: compute p in [0,255] (grid.y = 4),
// mirror-write conj(T[p][q]) to [(512-p)&511][(512-q)&511]. Row 256 = 0
// (handled at the T-FFT load). 64x64 tile per CTA, FFMA2 inner loop.
// ---------------------------------------------------------------------------
__global__ __launch_bounds__(128, 4) void tpart_kernel() {
    __shared__ float2 sE[16 * 64]; // ex chunk [kk][p]
    __shared__ float2 sF[16 * 64]; // ey chunk [kk][q]

    int p0 = blockIdx.y * 64;      // 0..192
    int q0 = blockIdx.x * 64;
    int m0 = blockIdx.z * (MSAMP / KSPLIT);
    int tid = threadIdx.x;
    int ti = tid >> 4;   // 0..7
    int tj = tid & 15;   // 0..15

    u64t acc[8][4];
#pragma unroll
    for (int a = 0; a < 8; a++)
#pragma unroll
        for (int c = 0; c < 4; c++) acc[a][c] = 0ull;

    for (int k0 = 0; k0 < MSAMP / KSPLIT; k0 += 16) {
        __syncthreads();
#pragma unroll
        for (int u = tid; u < 1024; u += 128) {
            int kk  = u >> 6;
            int idx = u & 63;
            int m   = m0 + k0 + kk;
            sE[u] = g_ex[m * NF + p0 + idx];
            sF[u] = g_ey[m * NF + q0 + idx];
        }
        __syncthreads();

        const float4* sF4 = reinterpret_cast<const float4*>(sF);
#pragma unroll
        for (int kk = 0; kk < 16; ++kk) {
            int wbase = (kk * 64 + tj * 4) >> 1;
            float4 w01 = sF4[wbase];
            float4 w23 = sF4[wbase + 1];
            u64t W1[4], W2[4];
            W1[0] = pk2(w01.x, w01.x); W2[0] = pk2(-w01.y, w01.y);
            W1[1] = pk2(w01.z, w01.z); W2[1] = pk2(-w01.w, w01.w);
            W1[2] = pk2(w23.x, w23.x); W2[2] = pk2(-w23.y, w23.y);
            W1[3] = pk2(w23.z, w23.z); W2[3] = pk2(-w23.w, w23.w);
#pragma unroll
            for (int a = 0; a < 8; a++) {
                float2 av = sE[kk * 64 + ti + 8 * a];
                u64t avs = pk2(av.x, av.y);
                u64t avr = pk2(av.y, av.x);
#pragma unroll
                for (int c = 0; c < 4; c++) {
                    fma2(acc[a][c], W1[c], avs);
                    fma2(acc[a][c], W2[c], avr);
                }
            }
        }
    }

    float2* outp = g_Tpart + blockIdx.z * NF2;
#pragma unroll
    for (int a = 0; a < 8; a++) {
        int p  = p0 + ti + 8 * a;             // 0..255
        int pm = (NF - p) & (NF - 1);
#pragma unroll
        for (int c = 0; c < 4; c++) {
            int q  = q0 + tj * 4 + c;
            int qm = (NF - q) & (NF - 1);
            float2 v = unpk2(acc[a][c]);
            outp[p * NF + q] = v;
            outp[pm * NF + qm] = make_float2(v.x, -v.y);
        }
    }
}

// ---------------------------------------------------------------------------
// Generic 512-pt Stockham radix-8 FFT pass. 64 threads/line, 8 lines/CTA
// (512 threads). Output is staged through smem and written as float4 bursts
// along the line axis -> fully coalesced transposed stores.
// MODE 0: x fwd pass1 (zero-pad load from xr/xi rows), -> buf1[v][i]
// MODE 1: x fwd pass2 (zero-pad load buf1[v][*]),      -> buf2[u][v]
// MODE 2: x inv pass1 (load buf2[u][*] * TFt[u][*]),   -> buf1[j][u], j<256
// MODE 3: x inv pass2 (load buf1[j][*]),               -> out[i][j], i<256, /512^2
// MODE 4: T pass1 (load sum of Tpart rows; row 256=0), -> Ttmp[v][p]
// MODE 5: T pass2 (load Ttmp[v][*]),                   -> TFt[u][v]
// ---------------------------------------------------------------------------
#define SPAD(x) ((x) + ((x) >> 3))
#define TSTRIDE 514   // transpose-stage line stride: 2*514 mod 16 = 4 -> gp banks {0,4,8,12}, conflict-free

template<int MODE, int DIR>
__global__ __launch_bounds__(512) void fft_pass_kernel(
    const float* __restrict__ xr, const float* __restrict__ xi,
    float2* __restrict__ out)
{
    __shared__ float2 s_tw[NF];
    __shared__ float2 s_buf[8][576];
    float2* sTr = &s_buf[0][0];    // reused as sT[line][k], stride TSTRIDE

    int t = threadIdx.x;
    int grp = t >> 6;          // line within CTA (0..7)
    int i   = t & 63;          // butterfly index

    s_tw[t] = g_tw[t];

    int line = blockIdx.x * 8 + grp;

    // ---- decode line, load 8 inputs: a[r] = in[i + 64r] ----
    float2 a[8];
    int b = 0, l2 = 0;
    if (MODE == 0) {
        b = line >> 8; l2 = line & 255;                 // l2 = image row i
        const float* pr = xr + ((b << 16) + (l2 << 8));
        const float* pi = xi + ((b << 16) + (l2 << 8));
#pragma unroll
        for (int r = 0; r < 8; r++) {
            if (r < 4) { int n = i + (r << 6); a[r] = make_float2(pr[n], pi[n]); }
            else a[r] = make_float2(0.f, 0.f);
        }
    } else if (MODE == 1) {
        b = line >> 9; l2 = line & 511;                 // l2 = v
        const float2* src = g_buf1 + b * NF2 + l2 * NF;
#pragma unroll
        for (int r = 0; r < 8; r++)
            a[r] = (r < 4) ? src[i + (r << 6)] : make_float2(0.f, 0.f);
    } else if (MODE == 2) {
        b = line >> 9; l2 = line & 511;                 // l2 = u
        const float2* src = g_buf2 + b * NF2 + l2 * NF;
        const float2* tf  = g_TFt + l2 * NF;            // TFt[u][v]
#pragma unroll
        for (int r = 0; r < 8; r++) {
            int n = i + (r << 6);
            a[r] = cmulf(src[n], tf[n]);
        }
    } else if (MODE == 3) {
        b = line >> 8; l2 = line & 255;                 // l2 = j
        const float2* src = g_buf1 + b * NF2 + l2 * NF;
#pragma unroll
        for (int r = 0; r < 8; r++) a[r] = src[i + (r << 6)];
    } else if (MODE == 4) {
        l2 = line;                                      // l2 = p
        if (l2 == 256) {
#pragma unroll
            for (int r = 0; r < 8; r++) a[r] = make_float2(0.f, 0.f);
        } else {
            const float2* src = g_Tpart + l2 * NF;
#pragma unroll
            for (int r = 0; r < 8; r++) {
                float2 s = make_float2(0.f, 0.f);
#pragma unroll
                for (int z = 0; z < KSPLIT; z++)
                    s = cadd(s, src[z * NF2 + i + (r << 6)]);
                a[r] = s;
            }
        }
    } else { // MODE 5
        l2 = line;                                      // l2 = v
        const float2* src = g_Ttmp + l2 * NF;
#pragma unroll
        for (int r = 0; r < 8; r++) a[r] = src[i + (r << 6)];
    }

    // ---- stage 0 (L=1) ----
    dft8<DIR>(a);
#pragma unroll
    for (int r = 0; r < 8; r++) s_buf[grp][SPAD(8 * i + r)] = a[r];
    __syncthreads();

    // ---- stage 1 (L=8): twiddle W512^{8*p*r}, p = i&7 ----
#pragma unroll
    for (int r = 0; r < 8; r++) a[r] = s_buf[grp][SPAD(i + 64 * r)];
    {
        int p = i & 7;
#pragma unroll
        for (int r = 1; r < 8; r++) a[r] = ctw<DIR>(a[r], s_tw[(p * r) << 3]);
    }
    dft8<DIR>(a);
    __syncthreads();
#pragma unroll
    for (int r = 0; r < 8; r++)
        s_buf[grp][SPAD(((i >> 3) << 6) + (r << 3) + (i & 7))] = a[r];
    __syncthreads();

    // ---- stage 2 (L=64): twiddle W512^{i*r} ----
#pragma unroll
    for (int r = 0; r < 8; r++) a[r] = s_buf[grp][SPAD(i + 64 * r)];
#pragma unroll
    for (int r = 1; r < 8; r++) a[r] = ctw<DIR>(a[r], s_tw[i * r]);
    dft8<DIR>(a);

    // ---- transpose through smem: sT[grp][k], k = r*64 + i ----
    __syncthreads();   // all stage-2 reads of s_buf complete
#pragma unroll
    for (int r = 0; r < 8; r++) sTr[grp * TSTRIDE + ((r << 6) + i)] = a[r];
    __syncthreads();

    // ---- coalesced output: float4 bursts along the line (l2) axis ----
    const int KMAX  = (MODE == 2 || MODE == 3) ? 256 : 512;
    const int l2b   = (MODE == 0 || MODE == 3) ? ((blockIdx.x * 8) & 255)
                    : (MODE == 1 || MODE == 2) ? ((blockIdx.x * 8) & 511)
                    : (blockIdx.x * 8);
    float2* dst;
    int rowstride;
    if (MODE == 0)      { dst = g_buf1 + b * NF2; rowstride = NF;  }
    else if (MODE == 1) { dst = g_buf2 + b * NF2; rowstride = NF;  }
    else if (MODE == 2) { dst = g_buf1 + b * NF2; rowstride = NF;  }
    else if (MODE == 3) { dst = out + (b << 16);  rowstride = 256; }
    else if (MODE == 4) { dst = g_Ttmp;           rowstride = NF;  }
    else                { dst = g_TFt;            rowstride = NF;  }

#pragma unroll
    for (int w = 0; w < KMAX / 128; w++) {
        int idx = w * 512 + t;
        int k   = idx >> 2;
        int gp  = idx & 3;
        float2 v0 = sTr[(2 * gp)     * TSTRIDE + k];
        float2 v1 = sTr[(2 * gp + 1) * TSTRIDE + k];
        if (MODE == 3) {
            const float s = 1.0f / 262144.0f;
            v0.x *= s; v0.y *= s; v1.x *= s; v1.y *= s;
        }
        float4* p4 = reinterpret_cast<float4*>(dst + k * rowstride + l2b + 2 * gp);
        *p4 = make_float4(v0.x, v0.y, v1.x, v1.y);
    }
}

// ---------------------------------------------------------------------------
extern "C" void kernel_launch(void* const* d_in, const int* in_sizes, int n_in,
                              void* d_out, int out_size)
{
    const float* xr      = (const float*)d_in[0];
    const float* xi      = (const float*)d_in[1];
    const float* samples = (const float*)d_in[2];
    const float* density = (const float*)d_in[3];
    float2* out = (float2*)d_out;

    tw_kernel<<<2, 256>>>();
    build_exp_kernel<<<MSAMP, 256>>>(samples, density);
    tpart_kernel<<<dim3(8, 4, KSPLIT), 128>>>();

    // FFT2 of Toeplitz kernel (treduce fused into MODE 4 load)
    fft_pass_kernel<4, 1><<<NF / 8, 512>>>(nullptr, nullptr, nullptr);
    fft_pass_kernel<5, 1><<<NF / 8, 512>>>(nullptr, nullptr, nullptr);

    // x: forward FFT2 (zero-padded), pointwise TF (in MODE 2 load),
    // inverse FFT2, crop + scale
    fft_pass_kernel<0, 1><<<BATCH * 256 / 8, 512>>>(xr, xi, nullptr);
    fft_pass_kernel<1, 1><<<BATCH * 512 / 8, 512>>>(nullptr, nullptr, nullptr);
    fft_pass_kernel<2, -1><<<BATCH * 512 / 8, 512>>>(nullptr, nullptr, nullptr);
    fft_pass_kernel<3, -1><<<BATCH * 256 / 8, 512>>>(nullptr, nullptr, out);
}